// round 16
// baseline (speedup 1.0000x reference)
#include <cuda_runtime.h>
#include <cuda_fp16.h>
#include <math.h>

#define N_NODES 30000
#define E_EDGES 480000
#define VDIM    512
#define HID     32

#define SCAN_BLK 512
#define NBLKS ((N_NODES + SCAN_BLK - 1) / SCAN_BLK)   // 59

// k_A interleaved roles: groups of 11 blocks = 10 vnorm + 1 aux
#define KA_GRID  4125      // 375 groups
#define HIST_BLKS 256
#define BN_BLKS   118
// k_B interleaved roles: groups of 17 = 16 fill + 1 mlp
#define FILL_BLKS 1875     // one edge per thread (1875*256 = 480000)
#define MLP_BLKS  118
#define KB_GRID   (118 * 17)   // 2006

typedef unsigned long long ull;

// packed f32x2 helpers (sm_103a FFMA2 path — only reachable via PTX)
__device__ __forceinline__ ull pack2(float2 f) {
    ull r; asm("mov.b64 %0, {%1, %2};" : "=l"(r) : "f"(f.x), "f"(f.y)); return r;
}
__device__ __forceinline__ float2 unpack2(ull v) {
    float2 f; asm("mov.b64 {%0, %1}, %2;" : "=f"(f.x), "=f"(f.y) : "l"(v)); return f;
}
#define FMUL2(d, a, b)    asm("mul.rn.f32x2 %0, %1, %2;"     : "=l"(d) : "l"(a), "l"(b))
#define FFMA2(d, a, b, c) asm("fma.rn.f32x2 %0, %1, %2, %3;" : "=l"(d) : "l"(a), "l"(b), "l"(c))
#define FADD2(d, a, b)    asm("add.rn.f32x2 %0, %1, %2;"     : "=l"(d) : "l"(a), "l"(b))

// ---- scratch (__device__ globals; no allocation allowed) ----
__device__ __half g_vh[N_NODES * VDIM];    // normalized visual, fp16 (30.7 MB)
__device__ float  g_p[N_NODES];
__device__ int    g_cnt[N_NODES];          // zeroed for next replay in k_B
__device__ int    g_rowstart[N_NODES + 1];
__device__ int    g_cursor[N_NODES];
__device__ int    g_csr[E_EDGES];          // src indices grouped by dst
__device__ int    g_bsum[NBLKS];
__device__ int    g_arrive;
__device__ float  g_sum[HID];
__device__ float  g_sumsq[HID];
__device__ float  g_scale[HID];
__device__ float  g_shift[HID];
__device__ float  g_u[HID];
__device__ float  g_c;

// ---------------------------------------------------------------------------
// K_A: interleaved  vnorm | hist | bnstats
// ---------------------------------------------------------------------------
__global__ void k_A(const float* __restrict__ visual,
                    const int* __restrict__ ei,
                    const float* __restrict__ x,
                    const float* __restrict__ w1,
                    const float* __restrict__ b1) {
    int b = blockIdx.x;
    int r = b % 11, q = b / 11;
    if (r < 10) {
        // ---- vnorm: warp per node ----
        int vb   = q * 10 + r;
        int gw   = (vb * blockDim.x + threadIdx.x) >> 5;
        int lane = threadIdx.x & 31;
        if (gw >= N_NODES) return;
        const float4* v = (const float4*)(visual + (size_t)gw * VDIM);
        float4 f[4];
        float s = 0.f;
#pragma unroll
        for (int i = 0; i < 4; i++) {
            f[i] = v[i * 32 + lane];
            s = fmaf(f[i].x, f[i].x, s); s = fmaf(f[i].y, f[i].y, s);
            s = fmaf(f[i].z, f[i].z, s); s = fmaf(f[i].w, f[i].w, s);
        }
#pragma unroll
        for (int off = 16; off > 0; off >>= 1) s += __shfl_xor_sync(0xffffffffu, s, off);
        float rn = 1.0f / fmaxf(sqrtf(s), 1e-8f);
        __half2* out = (__half2*)(g_vh + (size_t)gw * VDIM);
#pragma unroll
        for (int i = 0; i < 4; i++) {
            __half2 h0 = __floats2half2_rn(f[i].x * rn, f[i].y * rn);
            __half2 h1 = __floats2half2_rn(f[i].z * rn, f[i].w * rn);
            uint2 pk;
            pk.x = *(unsigned int*)&h0;
            pk.y = *(unsigned int*)&h1;
            *(uint2*)(out + i * 64 + lane * 2) = pk;
        }
    } else if (q < HIST_BLKS) {
        // ---- hist ----
        int i = q * blockDim.x + threadIdx.x;
        int stride = HIST_BLKS * blockDim.x;
        for (int e = i; e < E_EDGES; e += stride)
            atomicAdd(&g_cnt[ei[E_EDGES + e]], 1);
    } else if (q < HIST_BLKS + BN_BLKS) {
        // ---- bnstats ----
        int n = (q - HIST_BLKS) * blockDim.x + threadIdx.x;
        int lane = threadIdx.x & 31;
        bool valid = (n < N_NODES);
        float x0 = 0.f, x1 = 0.f;
        if (valid) { x0 = x[2 * n]; x1 = x[2 * n + 1]; }
#pragma unroll
        for (int k = 0; k < HID; k++) {
            float h = valid ? fmaf(w1[2 * k], x0, fmaf(w1[2 * k + 1], x1, b1[k])) : 0.f;
            float s = h, s2 = h * h;
#pragma unroll
            for (int off = 16; off > 0; off >>= 1) {
                s  += __shfl_xor_sync(0xffffffffu, s,  off);
                s2 += __shfl_xor_sync(0xffffffffu, s2, off);
            }
            if (lane == 0) {
                atomicAdd(&g_sum[k], s);
                atomicAdd(&g_sumsq[k], s2);
            }
        }
    }
}

// ---------------------------------------------------------------------------
// K_scanprep: blocks [0,59) grid-cooperative exclusive scan; block 59 = prep.
// ---------------------------------------------------------------------------
__global__ void k_scanprep(const float* __restrict__ gamma,
                           const float* __restrict__ beta,
                           const float* __restrict__ wc,
                           const float* __restrict__ bc,
                           const float* __restrict__ wp,
                           const float* __restrict__ bp) {
    int b = blockIdx.x;
    if (b == NBLKS) {
        int k = threadIdx.x;
        if (k >= HID) return;
        const float invN = 1.0f / (float)N_NODES;
        float mu  = g_sum[k] * invN;
        float var = g_sumsq[k] * invN - mu * mu;
        float rstd = rsqrtf(var + 1e-5f);
        float sc = rstd * gamma[k];
        g_scale[k] = sc;
        g_shift[k] = beta[k] - mu * sc;
        float u = 0.f;
#pragma unroll
        for (int j = 0; j < HID; j++) u = fmaf(wp[j], wc[j * HID + k], u);
        g_u[k] = u;
        if (k == 0) {
            float c = bp[0];
#pragma unroll
            for (int j = 0; j < HID; j++) c = fmaf(wp[j], bc[j], c);
            g_c = c;
        }
        return;
    }

    __shared__ int wsum[SCAN_BLK / 32 + 1];
    __shared__ int s_boff;
    int tid = threadIdx.x, lane = tid & 31, wid = tid >> 5;
    int i = b * SCAN_BLK + tid;
    int v = (i < N_NODES) ? g_cnt[i] : 0;
    int xv = v;
#pragma unroll
    for (int off = 1; off < 32; off <<= 1) {
        int y = __shfl_up_sync(0xffffffffu, xv, off);
        if (lane >= off) xv += y;
    }
    if (lane == 31) wsum[wid] = xv;
    __syncthreads();
    if (tid == 0) {
        int run = 0;
#pragma unroll
        for (int k = 0; k < SCAN_BLK / 32; k++) { int t = wsum[k]; wsum[k] = run; run += t; }
        g_bsum[b] = run;
        __threadfence();
        atomicAdd(&g_arrive, 1);
    }
    __syncthreads();
    int local_excl = xv - v + wsum[wid];

    if (tid == 0) {
        while (*(volatile int*)&g_arrive != NBLKS) { /* spin */ }
    }
    __syncthreads();
    __threadfence();

    if (wid == 0) {
        int a0 = (lane < b) ? g_bsum[lane] : 0;
        int a1 = (lane + 32 < b) ? g_bsum[lane + 32] : 0;
        int t = a0 + a1;
#pragma unroll
        for (int off = 16; off > 0; off >>= 1) t += __shfl_xor_sync(0xffffffffu, t, off);
        if (lane == 0) s_boff = t;
    }
    __syncthreads();

    if (i < N_NODES) {
        int rr = local_excl + s_boff;
        g_rowstart[i] = rr;
        g_cursor[i] = rr;
    }
    if (b == NBLKS - 1 && tid == 0) g_rowstart[N_NODES] = E_EDGES;
}

// ---------------------------------------------------------------------------
// K_B: interleaved  fill (one edge per thread) | mlp (+ re-init for replay)
// ---------------------------------------------------------------------------
__global__ void k_B(const int* __restrict__ ei,
                    const float* __restrict__ x,
                    const float* __restrict__ w1,
                    const float* __restrict__ b1,
                    const float* __restrict__ prelu_a,
                    const float* __restrict__ w2,
                    const float* __restrict__ b2) {
    __shared__ float swu[HID];
    __shared__ float ssc[HID], ssh[HID];
    __shared__ float sconst;
    int b = blockIdx.x;
    int r = b % 17, q = b / 17;
    if (r < 16) {
        int fb = q * 16 + r;
        if (fb >= FILL_BLKS) return;
        int e = fb * blockDim.x + threadIdx.x;   // one edge per thread
        int dst = ei[E_EDGES + e];
        int src = ei[e];
        int pos = atomicAdd(&g_cursor[dst], 1);
        g_csr[pos] = src;
    } else {
        if (threadIdx.x < HID) {
            int k = threadIdx.x;
            float wu = 0.f;
#pragma unroll
            for (int j = 0; j < HID; j++) wu = fmaf(g_u[j], w2[j * HID + k], wu);
            swu[k] = wu;
            ssc[k] = g_scale[k];
            ssh[k] = g_shift[k];
            if (k == 0) {
                float c2 = 0.f;
#pragma unroll
                for (int j = 0; j < HID; j++) c2 = fmaf(g_u[j], b2[j], c2);
                sconst = c2;
            }
        }
        __syncthreads();

        // re-init consumed accumulators for the NEXT replay
        if (q == 0) {
            if (threadIdx.x < HID) { g_sum[threadIdx.x] = 0.f; g_sumsq[threadIdx.x] = 0.f; }
            if (threadIdx.x == HID) g_arrive = 0;
        }

        int n = q * blockDim.x + threadIdx.x;
        if (n >= N_NODES) return;
        g_cnt[n] = 0;                              // re-init for next replay
        float a = prelu_a[0];
        float x0 = x[2 * n], x1 = x[2 * n + 1];
        float p = sconst;
#pragma unroll
        for (int k = 0; k < HID; k++) {
            float h1 = fmaf(w1[2 * k], x0, fmaf(w1[2 * k + 1], x1, b1[k]));
            float h  = fmaf(h1, ssc[k], ssh[k]);
            float hp = (h >= 0.f) ? h : a * h;
            p = fmaf(hp, swu[k], p);
        }
        g_p[n] = p;
    }
}

// ---------------------------------------------------------------------------
// K_agg: warp per dst node, 64-thread blocks, TWO edges per iteration.
//  - dst slice pre-converted + packed into 8 f32x2 registers (once)
//  - per iteration: all 4x16B loads for both edges issued back-to-back
//    (2x memory-level parallelism vs single-edge pipeline)
//  - odd tail handled branchlessly: clamped shuffle index + zero weight
// ---------------------------------------------------------------------------
__global__ void __launch_bounds__(64) k_agg(float* __restrict__ out) {
    int gw   = (blockIdx.x * blockDim.x + threadIdx.x) >> 5;
    int lane = threadIdx.x & 31;
    if (gw >= N_NODES) return;

    int beg = g_rowstart[gw];
    int end = g_rowstart[gw + 1];

    const char* vb0 = (const char*)g_vh + lane * 16;   // lane's first 16B slot
    const char* vb1 = vb0 + 512;                       // lane's second 16B slot

    // preload + convert + pack dst slice (once per node)
    uint4 du0 = __ldg((const uint4*)(vb0 + ((size_t)gw << 10)));
    uint4 du1 = __ldg((const uint4*)(vb1 + ((size_t)gw << 10)));
    ull D[8];
    D[0] = pack2(__half22float2(*(__half2*)&du0.x));
    D[1] = pack2(__half22float2(*(__half2*)&du0.y));
    D[2] = pack2(__half22float2(*(__half2*)&du0.z));
    D[3] = pack2(__half22float2(*(__half2*)&du0.w));
    D[4] = pack2(__half22float2(*(__half2*)&du1.x));
    D[5] = pack2(__half22float2(*(__half2*)&du1.y));
    D[6] = pack2(__half22float2(*(__half2*)&du1.z));
    D[7] = pack2(__half22float2(*(__half2*)&du1.w));

    float acc = 0.f;

    for (int base = beg; base < end; base += 32) {
        int cnt = min(32, end - base);
        int   off = 0;
        float ps  = 0.f;
        if (lane < cnt) {
            int s = __ldg(&g_csr[base + lane]);
            off = s << 10;                 // byte offset of row (1024 B/row)
            ps  = __ldg(&g_p[s]);
        }

        for (int j = 0; j < cnt; j += 2) {
            int j1 = (j + 1 < cnt) ? (j + 1) : j;        // clamped tail index
            int   o0 = __shfl_sync(0xffffffffu, off, j);
            int   o1 = __shfl_sync(0xffffffffu, off, j1);
            float p0 = __shfl_sync(0xffffffffu, ps, j);
            float p1 = (j + 1 < cnt) ? __shfl_sync(0xffffffffu, ps, j1) : 0.f;

            // issue all four 16B loads back-to-back (4x MLP)
            uint4 a0 = *(const uint4*)(vb0 + o0);
            uint4 a1 = *(const uint4*)(vb1 + o0);
            uint4 b0 = *(const uint4*)(vb0 + o1);
            uint4 b1 = *(const uint4*)(vb1 + o1);

            ull sv, cA, cB, cT;
            // edge j
            sv = pack2(__half22float2(*(__half2*)&a0.x)); FMUL2(cA, sv, D[0]);
            sv = pack2(__half22float2(*(__half2*)&a0.y)); FMUL2(cB, sv, D[1]);
            sv = pack2(__half22float2(*(__half2*)&a0.z)); FFMA2(cA, sv, D[2], cA);
            sv = pack2(__half22float2(*(__half2*)&a0.w)); FFMA2(cB, sv, D[3], cB);
            sv = pack2(__half22float2(*(__half2*)&a1.x)); FFMA2(cA, sv, D[4], cA);
            sv = pack2(__half22float2(*(__half2*)&a1.y)); FFMA2(cB, sv, D[5], cB);
            sv = pack2(__half22float2(*(__half2*)&a1.z)); FFMA2(cA, sv, D[6], cA);
            sv = pack2(__half22float2(*(__half2*)&a1.w)); FFMA2(cB, sv, D[7], cB);
            FADD2(cT, cA, cB);
            float2 t = unpack2(cT);
            acc = fmaf(p0, t.x + t.y, acc);
            // edge j+1 (weight 0 on odd tail -> contributes exactly 0)
            sv = pack2(__half22float2(*(__half2*)&b0.x)); FMUL2(cA, sv, D[0]);
            sv = pack2(__half22float2(*(__half2*)&b0.y)); FMUL2(cB, sv, D[1]);
            sv = pack2(__half22float2(*(__half2*)&b0.z)); FFMA2(cA, sv, D[2], cA);
            sv = pack2(__half22float2(*(__half2*)&b0.w)); FFMA2(cB, sv, D[3], cB);
            sv = pack2(__half22float2(*(__half2*)&b1.x)); FFMA2(cA, sv, D[4], cA);
            sv = pack2(__half22float2(*(__half2*)&b1.y)); FFMA2(cB, sv, D[5], cB);
            sv = pack2(__half22float2(*(__half2*)&b1.z)); FFMA2(cA, sv, D[6], cA);
            sv = pack2(__half22float2(*(__half2*)&b1.w)); FFMA2(cB, sv, D[7], cB);
            FADD2(cT, cA, cB);
            t = unpack2(cT);
            acc = fmaf(p1, t.x + t.y, acc);
        }
    }

#pragma unroll
    for (int off = 16; off > 0; off >>= 1) acc += __shfl_xor_sync(0xffffffffu, acc, off);

    if (lane == 0) {
        float deg = (float)(end - beg);
        out[gw] = acc / fmaxf(deg, 1.0f) + g_c;
    }
}

// ---------------------------------------------------------------------------
extern "C" void kernel_launch(void* const* d_in, const int* in_sizes, int n_in,
                              void* d_out, int out_size) {
    const float* x       = (const float*)d_in[0];
    const float* visual  = (const float*)d_in[1];
    const int*   ei      = (const int*)d_in[2];
    const float* w1      = (const float*)d_in[3];
    const float* b1      = (const float*)d_in[4];
    const float* gamma   = (const float*)d_in[5];
    const float* beta    = (const float*)d_in[6];
    const float* prelu_a = (const float*)d_in[7];
    const float* w2      = (const float*)d_in[8];
    const float* b2      = (const float*)d_in[9];
    const float* wc      = (const float*)d_in[10];
    const float* bc      = (const float*)d_in[11];
    const float* wp      = (const float*)d_in[12];
    const float* bp      = (const float*)d_in[13];
    float*       out     = (float*)d_out;

    k_A<<<KA_GRID, 256>>>(visual, ei, x, w1, b1);
    k_scanprep<<<NBLKS + 1, SCAN_BLK>>>(gamma, beta, wc, bc, wp, bp);
    k_B<<<KB_GRID, 256>>>(ei, x, w1, b1, prelu_a, w2, b2);
    k_agg<<<(N_NODES * 32 + 63) / 64, 64>>>(out);
}